// round 13
// baseline (speedup 1.0000x reference)
#include <cuda_runtime.h>
#include <cstdint>

#define B_TOTAL 262144
#define TPB 256
#define ROWS_CTA 128
#define NBLK (B_TOTAL / ROWS_CTA)   // 2048

#define WT_STRIDE 72                 // weights k-major; banks (8q+g) conflict-free for B-frags
#define WT_LAYER (64 * WT_STRIDE)    // 4608
#define BC_OFF (3 * WT_LAYER)        // 13824: bc[3][128] = bias|c0
#define MSK_OFF (BC_OFF + 384)       // 14208: ull msk[2][128] (512 floats)
#define X_STRIDE 68                  // banks (4g+q) conflict-free for A-frags
#define P_OFF (MSK_OFF + 512)        // X buffers: P, Q, R (128 x 68)
#define Q_OFF (P_OFF + ROWS_CTA * X_STRIDE)
#define R_OFF (Q_OFF + ROWS_CTA * X_STRIDE)
#define SMEM_FLOATS (R_OFF + ROWS_CTA * X_STRIDE)   // 40832
#define SMEM_BYTES (SMEM_FLOATS * 4)                // 163328 -> 1 CTA/SM

typedef unsigned long long ull;

__device__ __forceinline__ void ffma2(ull& d, ull a, ull b) {
    asm("fma.rn.f32x2 %0, %1, %2, %0;" : "+l"(d) : "l"(a), "l"(b));
}
__device__ __forceinline__ ull pack2(float lo, float hi) {
    ull r;
    asm("mov.b64 %0, {%1, %2};" : "=l"(r) : "f"(lo), "f"(hi));
    return r;
}
__device__ __forceinline__ float2 unpk(ull v) {
    float lo, hi;
    asm("mov.b64 {%0, %1}, %2;" : "=f"(lo), "=f"(hi) : "l"(v));
    return make_float2(lo, hi);
}
__device__ __forceinline__ uint32_t cvt_tf32(float x) {
    uint32_t r;
    asm("cvt.rna.tf32.f32 %0, %1;" : "=r"(r) : "f"(x));
    return r;
}
// m16n8k8 TF32 MMA, C += A*B (fp32 accumulate)
__device__ __forceinline__ void mma_tf32(float* c,
    uint32_t a0, uint32_t a1, uint32_t a2, uint32_t a3,
    uint32_t b0, uint32_t b1) {
    asm volatile(
        "mma.sync.aligned.m16n8k8.row.col.f32.tf32.tf32.f32 "
        "{%0,%1,%2,%3}, {%4,%5,%6,%7}, {%8,%9}, {%0,%1,%2,%3};"
        : "+f"(c[0]), "+f"(c[1]), "+f"(c[2]), "+f"(c[3])
        : "r"(a0), "r"(a1), "r"(a2), "r"(a3), "r"(b0), "r"(b1));
}

// ---------------------------------------------------------------------------
// Scalar forward mask layer (cuBLAS-exact): FFMA2 on OUTPUT pairs, each lane a
// single sequential k-ascending chain (init t*c0[j]; fmaf k-asc; + bias[j]).
// Bit-identical to R12 (passed, rel 2.7e-7). Warp w owns rows [16w,16w+16).
// Thread: rows rb+4i (rb=16w+(lane&3)), cols J0..J0+7 (J0=8*(lane>>2)).
// SPLIT=0: store fp32 to O1.  SPLIT=1: store tf32-hi to O1, tf32-lo to O2.
// Mask bytes written to mskb[(row)*8 + J0/8].
// ---------------------------------------------------------------------------
template <int SPLIT>
__device__ __forceinline__ void scalar_fwd(
    const float* __restrict__ Wt, const float* __restrict__ bcL,
    const float* __restrict__ Xin, float* __restrict__ O1,
    float* __restrict__ O2, unsigned char* __restrict__ mskb,
    float t, int w, int lane) {
    const int rb = 16 * w + (lane & 3);
    const int J0 = (lane >> 2) * 8;
    ull C[4][4];
#pragma unroll
    for (int jp = 0; jp < 4; jp++) {
        ull cj = pack2(t * bcL[64 + J0 + 2 * jp], t * bcL[64 + J0 + 2 * jp + 1]);
#pragma unroll
        for (int i = 0; i < 4; i++) C[i][jp] = cj;
    }
#pragma unroll 1
    for (int k4 = 0; k4 < 16; k4++) {
        float4 a4[4];
#pragma unroll
        for (int i = 0; i < 4; i++)
            a4[i] = *(const float4*)(Xin + (rb + 4 * i) * X_STRIDE + 4 * k4);
#pragma unroll
        for (int kk = 0; kk < 4; kk++) {
            int k = 4 * k4 + kk;
            const ulonglong2* bp = (const ulonglong2*)(Wt + k * WT_STRIDE + J0);
            ulonglong2 w01 = bp[0], w23 = bp[1];
            ull bq[4] = {w01.x, w01.y, w23.x, w23.y};
#pragma unroll
            for (int i = 0; i < 4; i++) {
                float a = (kk == 0) ? a4[i].x : (kk == 1) ? a4[i].y
                        : (kk == 2) ? a4[i].z : a4[i].w;
                ull ap = pack2(a, a);
#pragma unroll
                for (int jp = 0; jp < 4; jp++) ffma2(C[i][jp], ap, bq[jp]);
            }
        }
    }
#pragma unroll
    for (int i = 0; i < 4; i++) {
        int row = rb + 4 * i;
        float s[8];
        unsigned mbits = 0;
#pragma unroll
        for (int jp = 0; jp < 4; jp++) {
            float2 c = unpk(C[i][jp]);
            float v0 = c.x + bcL[J0 + 2 * jp];
            float v1 = c.y + bcL[J0 + 2 * jp + 1];
            if (v0 > 0.0f) mbits |= 1u << (2 * jp); else v0 = 0.0f;
            if (v1 > 0.0f) mbits |= 1u << (2 * jp + 1); else v1 = 0.0f;
            s[2 * jp] = v0; s[2 * jp + 1] = v1;
        }
        mskb[row * 8 + (J0 >> 3)] = (unsigned char)mbits;
        if (!SPLIT) {
            float* o = O1 + row * X_STRIDE + J0;
            *(float4*)(o) = make_float4(s[0], s[1], s[2], s[3]);
            *(float4*)(o + 4) = make_float4(s[4], s[5], s[6], s[7]);
        } else {
            float hi[8], lo[8];
#pragma unroll
            for (int b = 0; b < 8; b++) {
                hi[b] = __uint_as_float(cvt_tf32(s[b]));
                lo[b] = __uint_as_float(cvt_tf32(s[b] - hi[b]));
            }
            float* o1 = O1 + row * X_STRIDE + J0;
            float* o2 = O2 + row * X_STRIDE + J0;
            *(float4*)(o1) = make_float4(hi[0], hi[1], hi[2], hi[3]);
            *(float4*)(o1 + 4) = make_float4(hi[4], hi[5], hi[6], hi[7]);
            *(float4*)(o2) = make_float4(lo[0], lo[1], lo[2], lo[3]);
            *(float4*)(o2 + 4) = make_float4(lo[4], lo[5], lo[6], lo[7]);
        }
    }
}

// ---------------------------------------------------------------------------
// Tensor GEMM over warp strip rows [16w,16w+16): C = X * Wt (3xTF32 passes:
// Ahi*Bhi + Ahi*Blo + Alo*Bhi; B hi/lo derived from fp32 weights via cvt).
// MODE 0: z_dot -> +bias+t*c0, store fp32 to outQ.
// MODE 1: mask (mskL) then split-store hi->Phi, lo->Plo (in-place, warp-local).
// MODE 2: p = C; div = e.p with e from Qe; quad-reduce; write negdiv.
// ---------------------------------------------------------------------------
template <int MODE>
__device__ __forceinline__ void tensor_gemm(
    const float* __restrict__ Wt, float* __restrict__ Phi, float* __restrict__ Plo,
    const float* __restrict__ bcL, const ull* __restrict__ mskL,
    const float* __restrict__ Qe, float t, int w, int lane,
    float* __restrict__ outQ, float* __restrict__ negdiv, int rowbase) {
    const int g = lane >> 2, q = lane & 3;
    const int r0 = 16 * w + g;          // rows r0, r0+8
    float C[8][4];
#pragma unroll
    for (int nt = 0; nt < 8; nt++)
#pragma unroll
        for (int x = 0; x < 4; x++) C[nt][x] = 0.0f;
#pragma unroll 1
    for (int k8 = 0; k8 < 8; k8++) {
        int kb = 8 * k8 + q;
        uint32_t ah0 = __float_as_uint(Phi[r0 * X_STRIDE + kb]);
        uint32_t ah1 = __float_as_uint(Phi[(r0 + 8) * X_STRIDE + kb]);
        uint32_t ah2 = __float_as_uint(Phi[r0 * X_STRIDE + kb + 4]);
        uint32_t ah3 = __float_as_uint(Phi[(r0 + 8) * X_STRIDE + kb + 4]);
        uint32_t al0 = __float_as_uint(Plo[r0 * X_STRIDE + kb]);
        uint32_t al1 = __float_as_uint(Plo[(r0 + 8) * X_STRIDE + kb]);
        uint32_t al2 = __float_as_uint(Plo[r0 * X_STRIDE + kb + 4]);
        uint32_t al3 = __float_as_uint(Plo[(r0 + 8) * X_STRIDE + kb + 4]);
#pragma unroll
        for (int nt = 0; nt < 8; nt++) {
            int col = nt * 8 + g;
            float bw0 = Wt[(8 * k8 + q) * WT_STRIDE + col];
            float bw1 = Wt[(8 * k8 + q + 4) * WT_STRIDE + col];
            uint32_t bh0 = cvt_tf32(bw0), bh1 = cvt_tf32(bw1);
            uint32_t bl0 = cvt_tf32(bw0 - __uint_as_float(bh0));
            uint32_t bl1 = cvt_tf32(bw1 - __uint_as_float(bh1));
            mma_tf32(C[nt], ah0, ah1, ah2, ah3, bh0, bh1);
            mma_tf32(C[nt], ah0, ah1, ah2, ah3, bl0, bl1);
            mma_tf32(C[nt], al0, al1, al2, al3, bh0, bh1);
        }
    }
    if (MODE == 0) {
#pragma unroll
        for (int nt = 0; nt < 8; nt++) {
            int col = nt * 8 + 2 * q;
            float b0v = bcL[col] + t * bcL[64 + col];
            float b1v = bcL[col + 1] + t * bcL[64 + col + 1];
            *(float2*)(outQ + r0 * X_STRIDE + col) =
                make_float2(C[nt][0] + b0v, C[nt][1] + b1v);
            *(float2*)(outQ + (r0 + 8) * X_STRIDE + col) =
                make_float2(C[nt][2] + b0v, C[nt][3] + b1v);
        }
    } else if (MODE == 1) {
        ull m0 = mskL[r0], m1 = mskL[r0 + 8];
#pragma unroll
        for (int nt = 0; nt < 8; nt++) {
            int col = nt * 8 + 2 * q;
            float v00 = ((m0 >> col) & 1ull) ? C[nt][0] : 0.0f;
            float v01 = ((m0 >> (col + 1)) & 1ull) ? C[nt][1] : 0.0f;
            float v10 = ((m1 >> col) & 1ull) ? C[nt][2] : 0.0f;
            float v11 = ((m1 >> (col + 1)) & 1ull) ? C[nt][3] : 0.0f;
            float h00 = __uint_as_float(cvt_tf32(v00));
            float h01 = __uint_as_float(cvt_tf32(v01));
            float h10 = __uint_as_float(cvt_tf32(v10));
            float h11 = __uint_as_float(cvt_tf32(v11));
            *(float2*)(Phi + r0 * X_STRIDE + col) = make_float2(h00, h01);
            *(float2*)(Phi + (r0 + 8) * X_STRIDE + col) = make_float2(h10, h11);
            *(float2*)(Plo + r0 * X_STRIDE + col) = make_float2(
                __uint_as_float(cvt_tf32(v00 - h00)), __uint_as_float(cvt_tf32(v01 - h01)));
            *(float2*)(Plo + (r0 + 8) * X_STRIDE + col) = make_float2(
                __uint_as_float(cvt_tf32(v10 - h10)), __uint_as_float(cvt_tf32(v11 - h11)));
        }
    } else {
        float pg = 0.0f, pg8 = 0.0f;
#pragma unroll
        for (int nt = 0; nt < 8; nt++) {
            int col = nt * 8 + 2 * q;
            float2 e0 = *(const float2*)(Qe + r0 * X_STRIDE + col);
            float2 e1 = *(const float2*)(Qe + (r0 + 8) * X_STRIDE + col);
            pg = fmaf(e0.x, C[nt][0], pg);  pg = fmaf(e0.y, C[nt][1], pg);
            pg8 = fmaf(e1.x, C[nt][2], pg8); pg8 = fmaf(e1.y, C[nt][3], pg8);
        }
        pg += __shfl_xor_sync(0xffffffffu, pg, 1);
        pg += __shfl_xor_sync(0xffffffffu, pg, 2);
        pg8 += __shfl_xor_sync(0xffffffffu, pg8, 1);
        pg8 += __shfl_xor_sync(0xffffffffu, pg8, 2);
        if (q == 0) {
            negdiv[rowbase + r0] = -pg;
            negdiv[rowbase + r0 + 8] = -pg8;
        }
    }
}

__global__ void __launch_bounds__(TPB)
ode_kernel(const float* __restrict__ tptr, const float* __restrict__ z,
           const float* __restrict__ e,
           const float* __restrict__ W0, const float* __restrict__ b0,
           const float* __restrict__ W1, const float* __restrict__ b1,
           const float* __restrict__ W2, const float* __restrict__ b2,
           float* __restrict__ zdot, float* __restrict__ negdiv) {
    extern __shared__ float sm[];
    const int tid = threadIdx.x;
    const int lane = tid & 31, w = tid >> 5;
    float* bc = sm + BC_OFF;
    float* P = sm + P_OFF;
    float* Q = sm + Q_OFF;
    float* R = sm + R_OFF;
    unsigned char* mskb = (unsigned char*)(sm + MSK_OFF);
    const ull* msk0 = (const ull*)(sm + MSK_OFF);
    const ull* msk1 = msk0 + 128;
    const int rowbase = blockIdx.x * ROWS_CTA;

    // ---- Stage weights (k-major fp32) + bias/c0 ----
    {
        const float* Wg[3] = {W0, W1, W2};
        const float* bg[3] = {b0, b1, b2};
        for (int idx = tid; idx < 3 * 4096; idx += TPB) {
            int k = idx & 63, j = (idx >> 6) & 63, l = idx >> 12;
            sm[l * WT_LAYER + k * WT_STRIDE + j] = Wg[l][j * 65 + 1 + k];
        }
        if (tid < 192) {
            int l = tid >> 6, j = tid & 63;
            bc[l * 128 + j] = bg[l][j];
            bc[l * 128 + 64 + j] = Wg[l][j * 65];
        }
    }
    // ---- Stage z (fp32) into P: thread handles half a row ----
    {
        int row = tid >> 1, half = tid & 1;
        const float4* zsrc = (const float4*)(z + ((size_t)rowbase + row) * 64) + half * 8;
        float* pd = P + row * X_STRIDE + half * 32;
#pragma unroll
        for (int c = 0; c < 8; c++) *(float4*)(pd + 4 * c) = zsrc[c];
    }
    __syncthreads();

    const float t = tptr[0];

    // ---- Scalar forward mask layers (bit-exact) ----
    scalar_fwd<0>(sm, bc, P, Q, nullptr, mskb, t, w, lane);                  // h0 -> Q
    __syncthreads();
    scalar_fwd<1>(sm + WT_LAYER, bc + 128, Q, P, R, mskb + 1024, t, w, lane); // h1 hi->P lo->R
    __syncthreads();

    // ---- fwd L2 on tensor cores: z_dot -> Q ----
    tensor_gemm<0>(sm + 2 * WT_LAYER, P, R, bc + 256, nullptr, nullptr,
                   t, w, lane, Q, nullptr, 0);
    __syncthreads();

    // ---- z_dot flush ----
    {
        float4* dst = (float4*)(zdot + (size_t)rowbase * 64);
        for (int i4 = tid; i4 < ROWS_CTA * 16; i4 += TPB) {
            int r = i4 >> 4, c = (i4 & 15) << 2;
            dst[i4] = *(const float4*)(Q + r * X_STRIDE + c);
        }
    }
    __syncthreads();

    // ---- Stage e: hi->P, lo->R, fp32->Q (warp-local rows) ----
    {
        int row = tid >> 1, half = tid & 1;
        const float4* esrc = (const float4*)(e + ((size_t)rowbase + row) * 64) + half * 8;
        float* pd = P + row * X_STRIDE + half * 32;
        float* rd = R + row * X_STRIDE + half * 32;
        float* qd = Q + row * X_STRIDE + half * 32;
#pragma unroll
        for (int c = 0; c < 8; c++) {
            float4 v = esrc[c];
            *(float4*)(qd + 4 * c) = v;
            float h0 = __uint_as_float(cvt_tf32(v.x));
            float h1 = __uint_as_float(cvt_tf32(v.y));
            float h2 = __uint_as_float(cvt_tf32(v.z));
            float h3 = __uint_as_float(cvt_tf32(v.w));
            *(float4*)(pd + 4 * c) = make_float4(h0, h1, h2, h3);
            *(float4*)(rd + 4 * c) = make_float4(
                __uint_as_float(cvt_tf32(v.x - h0)), __uint_as_float(cvt_tf32(v.y - h1)),
                __uint_as_float(cvt_tf32(v.z - h2)), __uint_as_float(cvt_tf32(v.w - h3)));
        }
    }
    __syncwarp();

    // ---- Backward chain (warp-local strips, in-place P/R) ----
    tensor_gemm<1>(sm, P, R, nullptr, msk0, nullptr, t, w, lane, nullptr, nullptr, 0);
    __syncwarp();
    tensor_gemm<1>(sm + WT_LAYER, P, R, nullptr, msk1, nullptr, t, w, lane, nullptr, nullptr, 0);
    __syncwarp();
    tensor_gemm<2>(sm + 2 * WT_LAYER, P, R, nullptr, nullptr, Q, t, w, lane,
                   nullptr, negdiv, rowbase);
}

extern "C" void kernel_launch(void* const* d_in, const int* in_sizes, int n_in,
                              void* d_out, int out_size) {
    const float* t  = (const float*)d_in[0];
    const float* z  = (const float*)d_in[1];
    const float* e  = (const float*)d_in[2];
    const float* W0 = (const float*)d_in[3];
    const float* b0 = (const float*)d_in[4];
    const float* W1 = (const float*)d_in[5];
    const float* b1 = (const float*)d_in[6];
    const float* W2 = (const float*)d_in[7];
    const float* b2 = (const float*)d_in[8];

    float* zdot = (float*)d_out;                       // [B, 64]
    float* negdiv = zdot + (size_t)B_TOTAL * 64;       // [B, 1]

    cudaFuncSetAttribute(ode_kernel, cudaFuncAttributeMaxDynamicSharedMemorySize, SMEM_BYTES);
    ode_kernel<<<NBLK, TPB, SMEM_BYTES>>>(t, z, e, W0, b0, W1, b1, W2, b2, zdot, negdiv);
}

// round 14
// speedup vs baseline: 1.5481x; 1.5481x over previous
#include <cuda_runtime.h>
#include <cstdint>

#define B_TOTAL 262144
#define TPB 256
#define ROWS_CTA 128
#define NBLK (B_TOTAL / ROWS_CTA)      // 2048

#define WT_STRIDE 72                   // k-major weights; B-frag banks (8q+g) bijective
#define WT_LAYER (64 * WT_STRIDE)      // 4608
#define W01_OFF 0                      // fp32 W0,W1 (scalar mask layers)
#define WHI_OFF (2 * WT_LAYER)         // 9216: tf32-hi, 3 layers
#define WLO_OFF (WHI_OFF + 3 * WT_LAYER)  // 23040: tf32-lo, 3 layers
#define BC_OFF  (WLO_OFF + 3 * WT_LAYER)  // 36864: bc[3][128] = bias|c0
#define MSK_OFF (BC_OFF + 384)         // 37248: mask bytes, 2 layers x 128 rows x 8B
#define X_STRIDE 68                    // A-frag banks (4g+q) bijective
#define P_OFF (MSK_OFF + 512)          // 37760: plane P (fp32 / tf32-hi)
#define R_OFF (P_OFF + ROWS_CTA * X_STRIDE)   // 46464: plane R (fp32 h0 / tf32-lo)
#define SMEM_FLOATS (R_OFF + ROWS_CTA * X_STRIDE)  // 55168
#define SMEM_BYTES (SMEM_FLOATS * 4)   // 220672 -> 1 CTA/SM

typedef unsigned long long ull;

__device__ __forceinline__ void ffma2(ull& d, ull a, ull b) {
    asm("fma.rn.f32x2 %0, %1, %2, %0;" : "+l"(d) : "l"(a), "l"(b));
}
__device__ __forceinline__ ull pack2(float lo, float hi) {
    ull r;
    asm("mov.b64 %0, {%1, %2};" : "=l"(r) : "f"(lo), "f"(hi));
    return r;
}
__device__ __forceinline__ float2 unpk(ull v) {
    float lo, hi;
    asm("mov.b64 {%0, %1}, %2;" : "=f"(lo), "=f"(hi) : "l"(v));
    return make_float2(lo, hi);
}
__device__ __forceinline__ uint32_t cvt_tf32(float x) {
    uint32_t r;
    asm("cvt.rna.tf32.f32 %0, %1;" : "=r"(r) : "f"(x));
    return r;
}
__device__ __forceinline__ void mma_tf32(float* c,
    uint32_t a0, uint32_t a1, uint32_t a2, uint32_t a3,
    uint32_t b0, uint32_t b1) {
    asm volatile(
        "mma.sync.aligned.m16n8k8.row.col.f32.tf32.tf32.f32 "
        "{%0,%1,%2,%3}, {%4,%5,%6,%7}, {%8,%9}, {%0,%1,%2,%3};"
        : "+f"(c[0]), "+f"(c[1]), "+f"(c[2]), "+f"(c[3])
        : "r"(a0), "r"(a1), "r"(a2), "r"(a3), "r"(b0), "r"(b1));
}

// ---------------------------------------------------------------------------
// Scalar forward mask layer (cuBLAS-exact; bit-identical to R12/R13 passing
// chains). Warp w rows [16w,16w+16); thread rows rb+4i, cols J0..J0+7.
// REM=0: store fp32 h -> O1.  REM=1: store tf32-hi -> O1, tf32-lo -> O2.
// ---------------------------------------------------------------------------
template <int REM>
__device__ __forceinline__ void scalar_fwd(
    const float* __restrict__ Wt, const float* __restrict__ bcL,
    const float* __restrict__ Xin, float* __restrict__ O1,
    float* __restrict__ O2, unsigned char* __restrict__ mskb,
    float t, int w, int lane) {
    const int rb = 16 * w + (lane & 3);
    const int J0 = (lane >> 2) * 8;
    ull C[4][4];
#pragma unroll
    for (int jp = 0; jp < 4; jp++) {
        ull cj = pack2(t * bcL[64 + J0 + 2 * jp], t * bcL[64 + J0 + 2 * jp + 1]);
#pragma unroll
        for (int i = 0; i < 4; i++) C[i][jp] = cj;
    }
#pragma unroll 1
    for (int k4 = 0; k4 < 16; k4++) {
        float4 a4[4];
#pragma unroll
        for (int i = 0; i < 4; i++)
            a4[i] = *(const float4*)(Xin + (rb + 4 * i) * X_STRIDE + 4 * k4);
#pragma unroll
        for (int kk = 0; kk < 4; kk++) {
            int k = 4 * k4 + kk;
            const ulonglong2* bp = (const ulonglong2*)(Wt + k * WT_STRIDE + J0);
            ulonglong2 w01 = bp[0], w23 = bp[1];
            ull bq[4] = {w01.x, w01.y, w23.x, w23.y};
#pragma unroll
            for (int i = 0; i < 4; i++) {
                float a = (kk == 0) ? a4[i].x : (kk == 1) ? a4[i].y
                        : (kk == 2) ? a4[i].z : a4[i].w;
                ull ap = pack2(a, a);
#pragma unroll
                for (int jp = 0; jp < 4; jp++) ffma2(C[i][jp], ap, bq[jp]);
            }
        }
    }
#pragma unroll
    for (int i = 0; i < 4; i++) {
        int row = rb + 4 * i;
        float s[8];
        unsigned mbits = 0;
#pragma unroll
        for (int jp = 0; jp < 4; jp++) {
            float2 c = unpk(C[i][jp]);
            float v0 = c.x + bcL[J0 + 2 * jp];
            float v1 = c.y + bcL[J0 + 2 * jp + 1];
            if (v0 > 0.0f) mbits |= 1u << (2 * jp); else v0 = 0.0f;
            if (v1 > 0.0f) mbits |= 1u << (2 * jp + 1); else v1 = 0.0f;
            s[2 * jp] = v0; s[2 * jp + 1] = v1;
        }
        mskb[row * 8 + (J0 >> 3)] = (unsigned char)mbits;
        if (!REM) {
            float* o = O1 + row * X_STRIDE + J0;
            *(float4*)(o) = make_float4(s[0], s[1], s[2], s[3]);
            *(float4*)(o + 4) = make_float4(s[4], s[5], s[6], s[7]);
        } else {
            float hi[8], lo[8];
#pragma unroll
            for (int b = 0; b < 8; b++) {
                hi[b] = __uint_as_float(cvt_tf32(s[b]));
                lo[b] = __uint_as_float(cvt_tf32(s[b] - hi[b]));
            }
            float* o1 = O1 + row * X_STRIDE + J0;
            float* o2 = O2 + row * X_STRIDE + J0;
            *(float4*)(o1) = make_float4(hi[0], hi[1], hi[2], hi[3]);
            *(float4*)(o1 + 4) = make_float4(hi[4], hi[5], hi[6], hi[7]);
            *(float4*)(o2) = make_float4(lo[0], lo[1], lo[2], lo[3]);
            *(float4*)(o2 + 4) = make_float4(lo[4], lo[5], lo[6], lo[7]);
        }
    }
}

// ---------------------------------------------------------------------------
// Tensor GEMM on warp strip rows [16w,16w+16): C = A * W (3xTF32, hi/lo
// PRE-SPLIT in smem -> no cvt in the loop). k8-outer: all frags loaded, then
// 24 MMAs = 8 independent chains.
// MODE 0: + bias + t*c0, write z_dot float2s DIRECT to gmem.
// MODE 1: mask, split-store hi->P lo->R in place (warp-local).
// MODE 2: p = C; div = e.p with e streamed from gmem; quad-reduce -> negdiv.
// ---------------------------------------------------------------------------
template <int MODE>
__device__ __forceinline__ void tensor_gemm(
    const float* __restrict__ Whi, const float* __restrict__ Wlo,
    float* __restrict__ P, float* __restrict__ R,
    const float* __restrict__ bcL, const ull* __restrict__ mskL,
    const float* __restrict__ egm, float* __restrict__ zdg,
    float t, int w, int lane, float* __restrict__ negdiv, int rowbase) {
    const int g = lane >> 2, q = lane & 3;
    const int r0 = 16 * w + g;
    float C[8][4];
#pragma unroll
    for (int nt = 0; nt < 8; nt++)
#pragma unroll
        for (int x = 0; x < 4; x++) C[nt][x] = 0.0f;
#pragma unroll 1
    for (int k8 = 0; k8 < 8; k8++) {
        int kb = 8 * k8 + q;
        uint32_t ah0 = __float_as_uint(P[r0 * X_STRIDE + kb]);
        uint32_t ah1 = __float_as_uint(P[(r0 + 8) * X_STRIDE + kb]);
        uint32_t ah2 = __float_as_uint(P[r0 * X_STRIDE + kb + 4]);
        uint32_t ah3 = __float_as_uint(P[(r0 + 8) * X_STRIDE + kb + 4]);
        uint32_t al0 = __float_as_uint(R[r0 * X_STRIDE + kb]);
        uint32_t al1 = __float_as_uint(R[(r0 + 8) * X_STRIDE + kb]);
        uint32_t al2 = __float_as_uint(R[r0 * X_STRIDE + kb + 4]);
        uint32_t al3 = __float_as_uint(R[(r0 + 8) * X_STRIDE + kb + 4]);
        uint32_t bh[8][2], bl[8][2];
#pragma unroll
        for (int nt = 0; nt < 8; nt++) {
            int col = nt * 8 + g;
            bh[nt][0] = __float_as_uint(Whi[kb * WT_STRIDE + col]);
            bh[nt][1] = __float_as_uint(Whi[(kb + 4) * WT_STRIDE + col]);
            bl[nt][0] = __float_as_uint(Wlo[kb * WT_STRIDE + col]);
            bl[nt][1] = __float_as_uint(Wlo[(kb + 4) * WT_STRIDE + col]);
        }
#pragma unroll
        for (int nt = 0; nt < 8; nt++) {
            mma_tf32(C[nt], ah0, ah1, ah2, ah3, bh[nt][0], bh[nt][1]);
            mma_tf32(C[nt], ah0, ah1, ah2, ah3, bl[nt][0], bl[nt][1]);
            mma_tf32(C[nt], al0, al1, al2, al3, bh[nt][0], bh[nt][1]);
        }
    }
    if (MODE == 0) {
#pragma unroll
        for (int nt = 0; nt < 8; nt++) {
            int col = nt * 8 + 2 * q;
            float b0v = bcL[col] + t * bcL[64 + col];
            float b1v = bcL[col + 1] + t * bcL[64 + col + 1];
            *(float2*)(zdg + (size_t)(rowbase + r0) * 64 + col) =
                make_float2(C[nt][0] + b0v, C[nt][1] + b1v);
            *(float2*)(zdg + (size_t)(rowbase + r0 + 8) * 64 + col) =
                make_float2(C[nt][2] + b0v, C[nt][3] + b1v);
        }
    } else if (MODE == 1) {
        ull m0 = mskL[r0], m1 = mskL[r0 + 8];
#pragma unroll
        for (int nt = 0; nt < 8; nt++) {
            int col = nt * 8 + 2 * q;
            float v00 = ((m0 >> col) & 1ull) ? C[nt][0] : 0.0f;
            float v01 = ((m0 >> (col + 1)) & 1ull) ? C[nt][1] : 0.0f;
            float v10 = ((m1 >> col) & 1ull) ? C[nt][2] : 0.0f;
            float v11 = ((m1 >> (col + 1)) & 1ull) ? C[nt][3] : 0.0f;
            float h00 = __uint_as_float(cvt_tf32(v00));
            float h01 = __uint_as_float(cvt_tf32(v01));
            float h10 = __uint_as_float(cvt_tf32(v10));
            float h11 = __uint_as_float(cvt_tf32(v11));
            *(float2*)(P + r0 * X_STRIDE + col) = make_float2(h00, h01);
            *(float2*)(P + (r0 + 8) * X_STRIDE + col) = make_float2(h10, h11);
            *(float2*)(R + r0 * X_STRIDE + col) = make_float2(
                __uint_as_float(cvt_tf32(v00 - h00)), __uint_as_float(cvt_tf32(v01 - h01)));
            *(float2*)(R + (r0 + 8) * X_STRIDE + col) = make_float2(
                __uint_as_float(cvt_tf32(v10 - h10)), __uint_as_float(cvt_tf32(v11 - h11)));
        }
    } else {
        float pg = 0.0f, pg8 = 0.0f;
#pragma unroll
        for (int nt = 0; nt < 8; nt++) {
            int col = nt * 8 + 2 * q;
            float2 e0 = *(const float2*)(egm + (size_t)(rowbase + r0) * 64 + col);
            float2 e1 = *(const float2*)(egm + (size_t)(rowbase + r0 + 8) * 64 + col);
            pg = fmaf(e0.x, C[nt][0], pg);  pg = fmaf(e0.y, C[nt][1], pg);
            pg8 = fmaf(e1.x, C[nt][2], pg8); pg8 = fmaf(e1.y, C[nt][3], pg8);
        }
        pg += __shfl_xor_sync(0xffffffffu, pg, 1);
        pg += __shfl_xor_sync(0xffffffffu, pg, 2);
        pg8 += __shfl_xor_sync(0xffffffffu, pg8, 1);
        pg8 += __shfl_xor_sync(0xffffffffu, pg8, 2);
        if (q == 0) {
            negdiv[rowbase + r0] = -pg;
            negdiv[rowbase + r0 + 8] = -pg8;
        }
    }
}

__global__ void __launch_bounds__(TPB)
ode_kernel(const float* __restrict__ tptr, const float* __restrict__ z,
           const float* __restrict__ e,
           const float* __restrict__ W0, const float* __restrict__ b0,
           const float* __restrict__ W1, const float* __restrict__ b1,
           const float* __restrict__ W2, const float* __restrict__ b2,
           float* __restrict__ zdot, float* __restrict__ negdiv) {
    extern __shared__ float sm[];
    const int tid = threadIdx.x;
    const int lane = tid & 31, w = tid >> 5;
    float* bc = sm + BC_OFF;
    float* P = sm + P_OFF;
    float* R = sm + R_OFF;
    unsigned char* mskb = (unsigned char*)(sm + MSK_OFF);
    const ull* msk0 = (const ull*)(sm + MSK_OFF);
    const ull* msk1 = msk0 + 128;
    const int rowbase = blockIdx.x * ROWS_CTA;

    // ---- Stage weights: fp32 (W0,W1) + pre-split tf32 hi/lo (all layers) ----
    {
        const float* Wg[3] = {W0, W1, W2};
        const float* bg[3] = {b0, b1, b2};
        for (int idx = tid; idx < 3 * 4096; idx += TPB) {
            int k = idx & 63, j = (idx >> 6) & 63, l = idx >> 12;
            float wv = Wg[l][j * 65 + 1 + k];
            int off = l * WT_LAYER + k * WT_STRIDE + j;
            if (l < 2) sm[W01_OFF + off] = wv;
            float hi = __uint_as_float(cvt_tf32(wv));
            sm[WHI_OFF + off] = hi;
            sm[WLO_OFF + off] = __uint_as_float(cvt_tf32(wv - hi));
        }
        if (tid < 192) {
            int l = tid >> 6, j = tid & 63;
            bc[l * 128 + j] = bg[l][j];
            bc[l * 128 + 64 + j] = Wg[l][j * 65];
        }
    }
    // ---- Stage z (fp32) into P ----
    {
        int row = tid >> 1, half = tid & 1;
        const float4* zsrc = (const float4*)(z + ((size_t)rowbase + row) * 64) + half * 8;
        float* pd = P + row * X_STRIDE + half * 32;
#pragma unroll
        for (int c = 0; c < 8; c++) *(float4*)(pd + 4 * c) = zsrc[c];
    }
    __syncthreads();

    const float t = tptr[0];

    // ---- Forward: scalar mask layers (bit-exact), then tensor L2 ----
    scalar_fwd<0>(sm + W01_OFF, bc, P, R, nullptr, mskb, t, w, lane);          // h0 -> R
    __syncwarp();
    scalar_fwd<1>(sm + W01_OFF + WT_LAYER, bc + 128, R, P, R, mskb + 1024,
                  t, w, lane);                                                  // h1 hi->P lo->R
    __syncwarp();
    tensor_gemm<0>(sm + WHI_OFF + 2 * WT_LAYER, sm + WLO_OFF + 2 * WT_LAYER,
                   P, R, bc + 256, nullptr, nullptr, zdot, t, w, lane, nullptr, rowbase);
    __syncwarp();

    // ---- Stage e: hi->P, lo->R (overwrites h1 after L2 consumed it) ----
    {
        int row = tid >> 1, half = tid & 1;
        const float4* esrc = (const float4*)(e + ((size_t)rowbase + row) * 64) + half * 8;
        float* pd = P + row * X_STRIDE + half * 32;
        float* rd = R + row * X_STRIDE + half * 32;
#pragma unroll
        for (int c = 0; c < 8; c++) {
            float4 v = esrc[c];
            float h0 = __uint_as_float(cvt_tf32(v.x));
            float h1 = __uint_as_float(cvt_tf32(v.y));
            float h2 = __uint_as_float(cvt_tf32(v.z));
            float h3 = __uint_as_float(cvt_tf32(v.w));
            *(float4*)(pd + 4 * c) = make_float4(h0, h1, h2, h3);
            *(float4*)(rd + 4 * c) = make_float4(
                __uint_as_float(cvt_tf32(v.x - h0)), __uint_as_float(cvt_tf32(v.y - h1)),
                __uint_as_float(cvt_tf32(v.z - h2)), __uint_as_float(cvt_tf32(v.w - h3)));
        }
    }
    __syncwarp();

    // ---- Backward chain (warp-local, in-place P/R) ----
    tensor_gemm<1>(sm + WHI_OFF, sm + WLO_OFF, P, R, nullptr, msk0,
                   nullptr, nullptr, t, w, lane, nullptr, rowbase);
    __syncwarp();
    tensor_gemm<1>(sm + WHI_OFF + WT_LAYER, sm + WLO_OFF + WT_LAYER, P, R,
                   nullptr, msk1, nullptr, nullptr, t, w, lane, nullptr, rowbase);
    __syncwarp();
    tensor_gemm<2>(sm + WHI_OFF + 2 * WT_LAYER, sm + WLO_OFF + 2 * WT_LAYER,
                   P, R, nullptr, nullptr, e, nullptr, t, w, lane, negdiv, rowbase);
}

extern "C" void kernel_launch(void* const* d_in, const int* in_sizes, int n_in,
                              void* d_out, int out_size) {
    const float* t  = (const float*)d_in[0];
    const float* z  = (const float*)d_in[1];
    const float* e  = (const float*)d_in[2];
    const float* W0 = (const float*)d_in[3];
    const float* b0 = (const float*)d_in[4];
    const float* W1 = (const float*)d_in[5];
    const float* b1 = (const float*)d_in[6];
    const float* W2 = (const float*)d_in[7];
    const float* b2 = (const float*)d_in[8];

    float* zdot = (float*)d_out;                       // [B, 64]
    float* negdiv = zdot + (size_t)B_TOTAL * 64;       // [B, 1]

    cudaFuncSetAttribute(ode_kernel, cudaFuncAttributeMaxDynamicSharedMemorySize, SMEM_BYTES);
    ode_kernel<<<NBLK, TPB, SMEM_BYTES>>>(t, z, e, W0, b0, W1, b1, W2, b2, zdot, negdiv);
}

// round 16
// speedup vs baseline: 1.7655x; 1.1404x over previous
#include <cuda_runtime.h>
#include <cstdint>

#define B_TOTAL 262144
#define TPB 256
#define ROWS_CTA 256
#define NBLK (B_TOTAL / ROWS_CTA)      // 1024
#define NB 4                           // 4 blocks of 64 rows per CTA

// ---- smem layout (floats) ----
#define WT_STRIDE 72                   // fp32 W0,W1 k-major (scalar layers)
#define WT_LAYER (64 * WT_STRIDE)      // 4608
#define W01_OFF 0                      // 2 layers fp32: 9216
// frag-ordered tf32 hi/lo cells: cell(k8,q,g) = 32 floats
//   [0..7]=hi krow kb nt0..7, [8..15]=hi krow kb+4, [16..23]=lo kb, [24..31]=lo kb+4
// strides: g:36, q:296, k8:1184
#define WF_OFF   9216
#define WF_LAYER 9472                  // 8 * 1184
#define BC_OFF   (WF_OFF + 3 * WF_LAYER)   // 37632: bc[3][128] = bias|c0
#define MSK_OFF  (BC_OFF + 384)            // 38016: ull msk[2buf][2layer][64]
#define P_OFF    (MSK_OFF + 512)           // 38528: planes[2buf][2][64*68]
#define X_STRIDE 68
#define PLANE    (64 * X_STRIDE)           // 4352
#define SMEM_FLOATS (P_OFF + 4 * PLANE)    // 55936
#define SMEM_BYTES (SMEM_FLOATS * 4)       // 223744 -> 1 CTA/SM

typedef unsigned long long ull;

__device__ __forceinline__ void ffma2(ull& d, ull a, ull b) {
    asm("fma.rn.f32x2 %0, %1, %2, %0;" : "+l"(d) : "l"(a), "l"(b));
}
__device__ __forceinline__ ull pack2(float lo, float hi) {
    ull r; asm("mov.b64 %0, {%1, %2};" : "=l"(r) : "f"(lo), "f"(hi)); return r;
}
__device__ __forceinline__ float2 unpk(ull v) {
    float lo, hi; asm("mov.b64 {%0, %1}, %2;" : "=f"(lo), "=f"(hi) : "l"(v));
    return make_float2(lo, hi);
}
__device__ __forceinline__ uint32_t cvt_tf32(float x) {
    uint32_t r; asm("cvt.rna.tf32.f32 %0, %1;" : "=r"(r) : "f"(x)); return r;
}
__device__ __forceinline__ void mma_tf32(float* c,
    uint32_t a0, uint32_t a1, uint32_t a2, uint32_t a3, uint32_t b0, uint32_t b1) {
    asm volatile(
        "mma.sync.aligned.m16n8k8.row.col.f32.tf32.tf32.f32 "
        "{%0,%1,%2,%3}, {%4,%5,%6,%7}, {%8,%9}, {%0,%1,%2,%3};"
        : "+f"(c[0]), "+f"(c[1]), "+f"(c[2]), "+f"(c[3])
        : "r"(a0), "r"(a1), "r"(a2), "r"(a3), "r"(b0), "r"(b1));
}
#define BAR_SYNC(id)   asm volatile("bar.sync %0, %1;" :: "r"(id), "r"(TPB) : "memory")
#define BAR_ARRIVE(id) asm volatile("bar.arrive %0, %1;" :: "r"(id), "r"(TPB) : "memory")

// ---------------------------------------------------------------------------
// Scalar forward mask layer (cuBLAS-exact; numerics identical to R12-R14
// passing kernels). Warp w (0-3) owns plane rows [16w,16w+16).
// REM=0: fp32 -> O1.  REM=1: tf32-hi -> O1, tf32-lo -> O2.
// ---------------------------------------------------------------------------
template <int REM>
__device__ __forceinline__ void scalar_fwd(
    const float* __restrict__ Wt, const float* __restrict__ bcL,
    const float* __restrict__ Xin, float* __restrict__ O1,
    float* __restrict__ O2, unsigned char* __restrict__ mskb,
    float t, int w, int lane) {
    const int rb = 16 * w + (lane & 3);
    const int J0 = (lane >> 2) * 8;
    ull C[4][4];
#pragma unroll
    for (int jp = 0; jp < 4; jp++) {
        ull cj = pack2(t * bcL[64 + J0 + 2 * jp], t * bcL[64 + J0 + 2 * jp + 1]);
#pragma unroll
        for (int i = 0; i < 4; i++) C[i][jp] = cj;
    }
#pragma unroll 1
    for (int k4 = 0; k4 < 16; k4++) {
        float4 a4[4];
#pragma unroll
        for (int i = 0; i < 4; i++)
            a4[i] = *(const float4*)(Xin + (rb + 4 * i) * X_STRIDE + 4 * k4);
#pragma unroll
        for (int kk = 0; kk < 4; kk++) {
            int k = 4 * k4 + kk;
            const ulonglong2* bp = (const ulonglong2*)(Wt + k * WT_STRIDE + J0);
            ulonglong2 w01 = bp[0], w23 = bp[1];
            ull bq[4] = {w01.x, w01.y, w23.x, w23.y};
#pragma unroll
            for (int i = 0; i < 4; i++) {
                float a = (kk == 0) ? a4[i].x : (kk == 1) ? a4[i].y
                        : (kk == 2) ? a4[i].z : a4[i].w;
                ull ap = pack2(a, a);
#pragma unroll
                for (int jp = 0; jp < 4; jp++) ffma2(C[i][jp], ap, bq[jp]);
            }
        }
    }
#pragma unroll
    for (int i = 0; i < 4; i++) {
        int row = rb + 4 * i;
        float s[8];
        unsigned mbits = 0;
#pragma unroll
        for (int jp = 0; jp < 4; jp++) {
            float2 c = unpk(C[i][jp]);
            float v0 = c.x + bcL[J0 + 2 * jp];
            float v1 = c.y + bcL[J0 + 2 * jp + 1];
            if (v0 > 0.0f) mbits |= 1u << (2 * jp); else v0 = 0.0f;
            if (v1 > 0.0f) mbits |= 1u << (2 * jp + 1); else v1 = 0.0f;
            s[2 * jp] = v0; s[2 * jp + 1] = v1;
        }
        mskb[row * 8 + (J0 >> 3)] = (unsigned char)mbits;
        if (!REM) {
            float* o = O1 + row * X_STRIDE + J0;
            *(float4*)(o) = make_float4(s[0], s[1], s[2], s[3]);
            *(float4*)(o + 4) = make_float4(s[4], s[5], s[6], s[7]);
        } else {
            float hi[8], lo[8];
#pragma unroll
            for (int b = 0; b < 8; b++) {
                hi[b] = __uint_as_float(cvt_tf32(s[b]));
                lo[b] = __uint_as_float(cvt_tf32(s[b] - hi[b]));
            }
            float* o1 = O1 + row * X_STRIDE + J0;
            float* o2 = O2 + row * X_STRIDE + J0;
            *(float4*)(o1) = make_float4(hi[0], hi[1], hi[2], hi[3]);
            *(float4*)(o1 + 4) = make_float4(hi[4], hi[5], hi[6], hi[7]);
            *(float4*)(o2) = make_float4(lo[0], lo[1], lo[2], lo[3]);
            *(float4*)(o2 + 4) = make_float4(lo[4], lo[5], lo[6], lo[7]);
        }
    }
}

// ---------------------------------------------------------------------------
// Tensor GEMM (3xTF32, frag-ordered weight cells, 8x LDS.128 per k8).
// R16 fix: cell float4s unpacked into proper 8-element register arrays
// (R15 read past a single float4 -- UB -> garbage B-frags for nt>=4).
// ---------------------------------------------------------------------------
template <int MODE>
__device__ __forceinline__ void tensor_gemm(
    const float* __restrict__ Wfrag,
    float* __restrict__ P, float* __restrict__ R,
    const float* __restrict__ bcL, const ull* __restrict__ mskL,
    const float* __restrict__ egm, float* __restrict__ zdg,
    float t, int ws, int lane, float* __restrict__ negdiv, int rowg) {
    const int g = lane >> 2, q = lane & 3;
    const int r0 = 16 * ws + g;
    float C[8][4];
#pragma unroll
    for (int nt = 0; nt < 8; nt++)
#pragma unroll
        for (int x = 0; x < 4; x++) C[nt][x] = 0.0f;
#pragma unroll 1
    for (int k8 = 0; k8 < 8; k8++) {
        int kb = 8 * k8 + q;
        uint32_t ah0 = __float_as_uint(P[r0 * X_STRIDE + kb]);
        uint32_t ah1 = __float_as_uint(P[(r0 + 8) * X_STRIDE + kb]);
        uint32_t ah2 = __float_as_uint(P[r0 * X_STRIDE + kb + 4]);
        uint32_t ah3 = __float_as_uint(P[(r0 + 8) * X_STRIDE + kb + 4]);
        uint32_t al0 = __float_as_uint(R[r0 * X_STRIDE + kb]);
        uint32_t al1 = __float_as_uint(R[(r0 + 8) * X_STRIDE + kb]);
        uint32_t al2 = __float_as_uint(R[r0 * X_STRIDE + kb + 4]);
        uint32_t al3 = __float_as_uint(R[(r0 + 8) * X_STRIDE + kb + 4]);
        const float4* cell = (const float4*)(Wfrag + k8 * 1184 + q * 296 + g * 36);
        float4 f0 = cell[0], f1 = cell[1], f2 = cell[2], f3 = cell[3];
        float4 f4 = cell[4], f5 = cell[5], f6 = cell[6], f7 = cell[7];
        float bhk[8]  = {f0.x, f0.y, f0.z, f0.w, f1.x, f1.y, f1.z, f1.w};
        float bhk4[8] = {f2.x, f2.y, f2.z, f2.w, f3.x, f3.y, f3.z, f3.w};
        float blk[8]  = {f4.x, f4.y, f4.z, f4.w, f5.x, f5.y, f5.z, f5.w};
        float blk4[8] = {f6.x, f6.y, f6.z, f6.w, f7.x, f7.y, f7.z, f7.w};
#pragma unroll
        for (int nt = 0; nt < 8; nt++) {
            uint32_t bh0 = __float_as_uint(bhk[nt]);
            uint32_t bh1 = __float_as_uint(bhk4[nt]);
            uint32_t bl0 = __float_as_uint(blk[nt]);
            uint32_t bl1 = __float_as_uint(blk4[nt]);
            mma_tf32(C[nt], ah0, ah1, ah2, ah3, bh0, bh1);
            mma_tf32(C[nt], ah0, ah1, ah2, ah3, bl0, bl1);
            mma_tf32(C[nt], al0, al1, al2, al3, bh0, bh1);
        }
    }
    if (MODE == 0) {
#pragma unroll
        for (int nt = 0; nt < 8; nt++) {
            int col = nt * 8 + 2 * q;
            float b0v = bcL[col] + t * bcL[64 + col];
            float b1v = bcL[col + 1] + t * bcL[64 + col + 1];
            *(float2*)(zdg + (size_t)(rowg + r0) * 64 + col) =
                make_float2(C[nt][0] + b0v, C[nt][1] + b1v);
            *(float2*)(zdg + (size_t)(rowg + r0 + 8) * 64 + col) =
                make_float2(C[nt][2] + b0v, C[nt][3] + b1v);
        }
    } else if (MODE == 1) {
        ull m0 = mskL[r0], m1 = mskL[r0 + 8];
#pragma unroll
        for (int nt = 0; nt < 8; nt++) {
            int col = nt * 8 + 2 * q;
            float v00 = ((m0 >> col) & 1ull) ? C[nt][0] : 0.0f;
            float v01 = ((m0 >> (col + 1)) & 1ull) ? C[nt][1] : 0.0f;
            float v10 = ((m1 >> col) & 1ull) ? C[nt][2] : 0.0f;
            float v11 = ((m1 >> (col + 1)) & 1ull) ? C[nt][3] : 0.0f;
            float h00 = __uint_as_float(cvt_tf32(v00));
            float h01 = __uint_as_float(cvt_tf32(v01));
            float h10 = __uint_as_float(cvt_tf32(v10));
            float h11 = __uint_as_float(cvt_tf32(v11));
            *(float2*)(P + r0 * X_STRIDE + col) = make_float2(h00, h01);
            *(float2*)(P + (r0 + 8) * X_STRIDE + col) = make_float2(h10, h11);
            *(float2*)(R + r0 * X_STRIDE + col) = make_float2(
                __uint_as_float(cvt_tf32(v00 - h00)), __uint_as_float(cvt_tf32(v01 - h01)));
            *(float2*)(R + (r0 + 8) * X_STRIDE + col) = make_float2(
                __uint_as_float(cvt_tf32(v10 - h10)), __uint_as_float(cvt_tf32(v11 - h11)));
        }
    } else {
        float pg = 0.0f, pg8 = 0.0f;
#pragma unroll
        for (int nt = 0; nt < 8; nt++) {
            int col = nt * 8 + 2 * q;
            float2 e0 = *(const float2*)(egm + (size_t)(rowg + r0) * 64 + col);
            float2 e1 = *(const float2*)(egm + (size_t)(rowg + r0 + 8) * 64 + col);
            pg = fmaf(e0.x, C[nt][0], pg);  pg = fmaf(e0.y, C[nt][1], pg);
            pg8 = fmaf(e1.x, C[nt][2], pg8); pg8 = fmaf(e1.y, C[nt][3], pg8);
        }
        pg += __shfl_xor_sync(0xffffffffu, pg, 1);
        pg += __shfl_xor_sync(0xffffffffu, pg, 2);
        pg8 += __shfl_xor_sync(0xffffffffu, pg8, 1);
        pg8 += __shfl_xor_sync(0xffffffffu, pg8, 2);
        if (q == 0) {
            negdiv[rowg + r0] = -pg;
            negdiv[rowg + r0 + 8] = -pg8;
        }
    }
}

__global__ void __launch_bounds__(TPB)
ode_kernel(const float* __restrict__ tptr, const float* __restrict__ z,
           const float* __restrict__ e,
           const float* __restrict__ W0, const float* __restrict__ b0,
           const float* __restrict__ W1, const float* __restrict__ b1,
           const float* __restrict__ W2, const float* __restrict__ b2,
           float* __restrict__ zdot, float* __restrict__ negdiv) {
    extern __shared__ float sm[];
    const int tid = threadIdx.x;
    const int lane = tid & 31, w = tid >> 5;
    float* bc = sm + BC_OFF;
    ull* msk = (ull*)(sm + MSK_OFF);          // [buf][layer][64]
    unsigned char* mskb = (unsigned char*)msk;

    // ---- Stage weights: fp32 W0/W1 + frag-ordered tf32 hi/lo cells ----
    {
        const float* Wg[3] = {W0, W1, W2};
        const float* bg[3] = {b0, b1, b2};
        for (int idx = tid; idx < 3 * 4096; idx += TPB) {
            int l = idx >> 12, rem = idx & 4095;
            int k = rem >> 6, j = rem & 63;
            float wv = Wg[l][j * 65 + 1 + k];
            if (l < 2) sm[W01_OFF + l * WT_LAYER + k * WT_STRIDE + j] = wv;
            float hi = __uint_as_float(cvt_tf32(wv));
            float lo = __uint_as_float(cvt_tf32(wv - hi));
            int k8 = k >> 3, kq = k & 3, kr = (k >> 2) & 1;
            int nt = j >> 3, g = j & 7;
            float* cell = sm + WF_OFF + l * WF_LAYER + k8 * 1184 + kq * 296 + g * 36;
            cell[kr * 8 + nt] = hi;
            cell[16 + kr * 8 + nt] = lo;
        }
        if (tid < 192) {
            int l = tid >> 6, j = tid & 63;
            bc[l * 128 + j] = bg[l][j];
            bc[l * 128 + 64 + j] = Wg[l][j * 65];
        }
    }
    __syncthreads();

    const float t = tptr[0];
    const int ctabase = blockIdx.x * ROWS_CTA;

    if (w < 4) {
        // ================= SCALAR (producer) warps 0-3 =================
        for (int b = 0; b < NB; b++) {
            int buf = b & 1;
            float* P = sm + P_OFF + buf * 2 * PLANE;
            float* R = P + PLANE;
            if (b >= 2) BAR_SYNC(3 + buf);           // wait buffer free
            // stage z strip rows [16w,16w+16) of block b into P (fp32)
            {
                int row = 16 * w + (lane >> 1), half = lane & 1;
                const float4* zs = (const float4*)(z + ((size_t)ctabase + b * 64 + row) * 64) + half * 8;
                float* pd = P + row * X_STRIDE + half * 32;
#pragma unroll
                for (int c = 0; c < 8; c++) *(float4*)(pd + 4 * c) = zs[c];
            }
            __syncwarp();
            unsigned char* mb0 = mskb + (size_t)(buf * 128) * 8;
            unsigned char* mb1 = mskb + (size_t)(buf * 128 + 64) * 8;
            scalar_fwd<0>(sm + W01_OFF, bc, P, R, nullptr, mb0, t, w, lane);  // h0 -> R
            __syncwarp();
            scalar_fwd<1>(sm + W01_OFF + WT_LAYER, bc + 128, R, P, R, mb1,
                          t, w, lane);                                         // h1 hi->P lo->R
            BAR_ARRIVE(1 + buf);                     // buffer full
        }
    } else {
        // ================= TENSOR (consumer) warps 4-7 =================
        const int ws = w - 4;
        for (int b = 0; b < NB; b++) {
            int buf = b & 1;
            float* P = sm + P_OFF + buf * 2 * PLANE;
            float* R = P + PLANE;
            int rowg = ctabase + b * 64;
            const ull* m0 = msk + buf * 128;
            const ull* m1 = m0 + 64;
            BAR_SYNC(1 + buf);                       // wait buffer full
            tensor_gemm<0>(sm + WF_OFF + 2 * WF_LAYER, P, R, bc + 256, nullptr,
                           nullptr, zdot, t, ws, lane, nullptr, rowg);
            __syncwarp();
            // stage e strip -> hi->P, lo->R
            {
                int row = 16 * ws + (lane >> 1), half = lane & 1;
                const float4* es = (const float4*)(e + ((size_t)rowg + row) * 64) + half * 8;
                float* pd = P + row * X_STRIDE + half * 32;
                float* rd = R + row * X_STRIDE + half * 32;
#pragma unroll
                for (int c = 0; c < 8; c++) {
                    float4 v = es[c];
                    float h0 = __uint_as_float(cvt_tf32(v.x));
                    float h1 = __uint_as_float(cvt_tf32(v.y));
                    float h2 = __uint_as_float(cvt_tf32(v.z));
                    float h3 = __uint_as_float(cvt_tf32(v.w));
                    *(float4*)(pd + 4 * c) = make_float4(h0, h1, h2, h3);
                    *(float4*)(rd + 4 * c) = make_float4(
                        __uint_as_float(cvt_tf32(v.x - h0)), __uint_as_float(cvt_tf32(v.y - h1)),
                        __uint_as_float(cvt_tf32(v.z - h2)), __uint_as_float(cvt_tf32(v.w - h3)));
                }
            }
            __syncwarp();
            tensor_gemm<1>(sm + WF_OFF, P, R, nullptr, m0, nullptr, nullptr,
                           t, ws, lane, nullptr, rowg);
            __syncwarp();
            tensor_gemm<1>(sm + WF_OFF + WF_LAYER, P, R, nullptr, m1, nullptr,
                           nullptr, t, ws, lane, nullptr, rowg);
            __syncwarp();
            tensor_gemm<2>(sm + WF_OFF + 2 * WF_LAYER, P, R, nullptr, nullptr,
                           e, nullptr, t, ws, lane, negdiv, rowg);
            BAR_ARRIVE(3 + buf);                     // buffer free
        }
    }
}

extern "C" void kernel_launch(void* const* d_in, const int* in_sizes, int n_in,
                              void* d_out, int out_size) {
    const float* t  = (const float*)d_in[0];
    const float* z  = (const float*)d_in[1];
    const float* e  = (const float*)d_in[2];
    const float* W0 = (const float*)d_in[3];
    const float* b0 = (const float*)d_in[4];
    const float* W1 = (const float*)d_in[5];
    const float* b1 = (const float*)d_in[6];
    const float* W2 = (const float*)d_in[7];
    const float* b2 = (const float*)d_in[8];

    float* zdot = (float*)d_out;                       // [B, 64]
    float* negdiv = zdot + (size_t)B_TOTAL * 64;       // [B, 1]

    cudaFuncSetAttribute(ode_kernel, cudaFuncAttributeMaxDynamicSharedMemorySize, SMEM_BYTES);
    ode_kernel<<<NBLK, TPB, SMEM_BYTES>>>(t, z, e, W0, b0, W1, b1, W2, b2, zdot, negdiv);
}